// round 14
// baseline (speedup 1.0000x reference)
#include <cuda_runtime.h>
#include <cuda_fp16.h>
#include <cstdint>

// Problem constants
#define B_ 2
#define H_ 8
#define N_ 512
#define D_ 16
#define E_ 128
#define HD 128
#define TM 32               // m-rows per tile
#define NTILES 16
#define THREADS 256

// smem layout (bytes). A/W rows are 128 fp16 = 256 B.
#define SM_Q     0                      // 512 B    q row, head-major
#define SM_S     512                    // 16384 B  scores [H][N]
#define SM_STAGE 17408                  // 16384 B  z fp32 staging [32][128] (cp.async dst)
#define SM_A     33792                  // 8192 B   z fp16 [32m][128k]
#define SM_W     41984                  // 65536 B  W fp16 [256n][128k] (d-permuted, interleaved)
#define SM_TOTAL 107520                 // -> 2 CTAs/SM

__device__ __forceinline__ uint32_t smem_u32(const void* p) {
    uint32_t r;
    asm("{ .reg .u64 t; cvta.to.shared.u64 t, %1; cvt.u32.u64 %0, t; }" : "=r"(r) : "l"(p));
    return r;
}
__device__ __forceinline__ void cp16(uint32_t s, const void* g) {
    asm volatile("cp.async.cg.shared.global [%0], [%1], 16;" :: "r"(s), "l"(g));
}
#define CP_COMMIT() asm volatile("cp.async.commit_group;" ::: "memory")
#define CP_WAIT0()  asm volatile("cp.async.wait_group 0;" ::: "memory")
__device__ __forceinline__ void ldsm_x4(uint32_t (&r)[4], uint32_t addr) {
    asm volatile("ldmatrix.sync.aligned.m8n8.x4.shared.b16 {%0,%1,%2,%3}, [%4];"
                 : "=r"(r[0]), "=r"(r[1]), "=r"(r[2]), "=r"(r[3]) : "r"(addr));
}
#define MMA_F16(d, a, b0v, b1v) \
    asm volatile("mma.sync.aligned.m16n8k16.row.col.f32.f16.f16.f32 " \
        "{%0,%1,%2,%3}, {%4,%5,%6,%7}, {%8,%9}, {%0,%1,%2,%3};" \
        : "+f"((d)[0]), "+f"((d)[1]), "+f"((d)[2]), "+f"((d)[3]) \
        : "r"((a)[0]), "r"((a)[1]), "r"((a)[2]), "r"((a)[3]), "r"(b0v), "r"(b1v))

__device__ __forceinline__ uint32_t pack_hf2(__half a, __half b) {
    __half2 p = __halves2half2(a, b);
    return *reinterpret_cast<uint32_t*>(&p);
}

__global__ void __launch_bounds__(THREADS, 2)
mixed_attn_dual(const float* __restrict__ q, const float* __restrict__ k,
                const float* __restrict__ v, const float* __restrict__ z,
                const float* __restrict__ Wz1, const float* __restrict__ Wz2,
                float* __restrict__ out)
{
    extern __shared__ char smem[];
    const uint32_t smem_base = smem_u32(smem);
    float* q_sm = (float*)(smem + SM_Q);
    float* s_sm = (float*)(smem + SM_S);

    const int tid  = threadIdx.x;
    const int wid  = tid >> 5;
    const int lane = tid & 31;
    const int g    = lane >> 2;
    const int tig  = lane & 3;
    const int n = blockIdx.x, b = blockIdx.y;

    const char* zbase = (const char*)(z + (((size_t)b * N_ + n) * N_) * E_);

    // =========================== PROLOGUE ===========================
    // issue cp.async for z tile 0 first (overlaps W build)
    {
        const uint32_t dst = smem_base + SM_STAGE + tid * 64;
        const char* src = zbase + tid * 64;
        #pragma unroll
        for (int i = 0; i < 4; i++) cp16(dst + i * 16, src + i * 16);
        CP_COMMIT();
    }
    // q row, head-major
    if (tid < HD) {
        int h = tid >> 4, d = tid & 15;
        q_sm[tid] = q[(((size_t)b * H_ + h) * N_ + n) * D_ + d];
    }
    // W -> fp16, d-PERMUTED columns (fragment (ntl,tig) sees d = 4*tig+ntl):
    //   nn: h = nn>>5, ntl = (nn>>3)&3, tg = (nn>>1)&3, src = nn&1
    //   source col c = h*16 + 4*tg + ntl of (src? Wz2 : Wz1). One row per thread.
    {
        const int nn = tid;
        const float* Wsrc = (nn & 1) ? Wz2 : Wz1;
        const int c = (nn >> 5) * 16 + ((nn >> 1) & 3) * 4 + ((nn >> 3) & 3);
        char* WH = smem + SM_W + nn * 256;
        const int xr = (nn & 7);
        #pragma unroll 4
        for (int e = 0; e < E_; e += 2) {
            float w0 = Wsrc[e * HD + c];
            float w1 = Wsrc[(e + 1) * HD + c];
            uint32_t hi = pack_hf2(__float2half_rn(w0), __float2half_rn(w1));
            int sw = ((((e >> 3) ^ xr) << 4)) + (e & 7) * 2;
            *(uint32_t*)(WH + sw) = hi;
        }
    }

    // warp tiling: 8 warps = 8 heads; warp tile 32m x 32n (head wid), K=128
    const int h     = wid;
    const int laneX = lane & 7;
    const uint32_t arow = smem_base + SM_A +
        (uint32_t)(((lane >> 3) & 1) * 8 + laneX) * 256;
    const int asel = lane >> 4;
    const uint32_t brow = smem_base + SM_W +
        (uint32_t)(h * 32 + ((lane >> 4) & 1) * 8 + laneX) * 256;
    const int bsel = (lane >> 3) & 1;

    // convert mapping: 8 threads per m-row, 16 e each
    const int crow = tid >> 3;
    const int ce0  = (tid & 3) << 5;       // unused placeholder (kept simple below)

    const float* kh = k + (((size_t)b * H_ + h) * N_) * D_;

    // ========================== MAIN LOOP ==========================
    for (int t = 0; t < NTILES; t++) {
        CP_WAIT0();
        __syncthreads();   // staging[t] visible to all; previous MMA done with A

        // ---- convert staging -> A (fp16, swizzled). row = tid>>3, e-range 16
        {
            const int row = crow;
            const int e0  = (tid & 7) * 16;
            const float4* st = (const float4*)(smem + SM_STAGE + row * 512 + e0 * 4);
            char* AH = smem + SM_A + row * 256;
            const int xr = row & 7;
            float4 f0 = st[0], f1 = st[1], f2 = st[2], f3 = st[3];
            #pragma unroll
            for (int j = 0; j < 4; j++) {
                float4 f = (j == 0) ? f0 : (j == 1) ? f1 : (j == 2) ? f2 : f3;
                const int e = e0 + j * 4;
                uint32_t h01 = pack_hf2(__float2half_rn(f.x), __float2half_rn(f.y));
                uint32_t h23 = pack_hf2(__float2half_rn(f.z), __float2half_rn(f.w));
                int sw = (((e >> 3) ^ xr) << 4) + (e & 4) * 2;
                *(uint2*)(AH + sw) = make_uint2(h01, h23);
            }
        }
        __syncthreads();   // A ready; staging free for next tile

        // ---- issue cp.async for tile t+1 (arrives during MMA)
        if (t + 1 < NTILES) {
            const uint32_t dst = smem_base + SM_STAGE + tid * 64;
            const char* src = zbase + (size_t)(t + 1) * (TM * E_ * 4) + tid * 64;
            #pragma unroll
            for (int i = 0; i < 4; i++) cp16(dst + i * 16, src + i * 16);
            CP_COMMIT();
        }

        // ---- MMA: 32m x 32n (head h), K=128
        float acc[2][4][4];
        #pragma unroll
        for (int mt = 0; mt < 2; mt++)
            #pragma unroll
            for (int nt = 0; nt < 4; nt++)
                #pragma unroll
                for (int i = 0; i < 4; i++) acc[mt][nt][i] = 0.f;

        #pragma unroll 2
        for (int ks = 0; ks < 8; ks++) {
            uint32_t ah[2][4];
            const uint32_t aoff = arow + ((uint32_t)((ks * 2 + asel) ^ laneX) << 4);
            ldsm_x4(ah[0], aoff);
            ldsm_x4(ah[1], aoff + 16 * 256);
            const uint32_t boff = ((uint32_t)((ks * 2 + bsel) ^ laneX) << 4);
            #pragma unroll
            for (int ntp = 0; ntp < 2; ntp++) {
                uint32_t bh[4];
                ldsm_x4(bh, brow + (uint32_t)ntp * (16 * 256) + boff);
                #pragma unroll
                for (int mt = 0; mt < 2; mt++) {
                    MMA_F16(acc[mt][2 * ntp],     ah[mt], bh[0], bh[1]);
                    MMA_F16(acc[mt][2 * ntp + 1], ah[mt], bh[2], bh[3]);
                }
            }
        }

        // ---- scores: fragment (ntl,tig) holds d = 4*tig+ntl -> one float4 k load per row
        {
            const float4 q4 = ((const float4*)(q_sm + h * 16))[tig];
            #pragma unroll
            for (int mt = 0; mt < 2; mt++) {
                #pragma unroll
                for (int r = 0; r < 2; r++) {
                    const int mg = t * TM + mt * 16 + r * 8 + g;
                    const float4 kv = *(const float4*)(kh + (size_t)mg * 16 + 4 * tig);
                    float s;
                    s  = (q4.x + acc[mt][0][2 * r]) * (kv.x + acc[mt][0][2 * r + 1]);
                    s += (q4.y + acc[mt][1][2 * r]) * (kv.y + acc[mt][1][2 * r + 1]);
                    s += (q4.z + acc[mt][2][2 * r]) * (kv.z + acc[mt][2][2 * r + 1]);
                    s += (q4.w + acc[mt][3][2 * r]) * (kv.w + acc[mt][3][2 * r + 1]);
                    s += __shfl_xor_sync(0xffffffffu, s, 1);
                    s += __shfl_xor_sync(0xffffffffu, s, 2);
                    if (tig == 0)
                        s_sm[h * N_ + mg] = s * 0.25f;   // 1/sqrt(D), D=16
                }
            }
        }
    }
    __syncthreads();   // all scores written

    // =========================== SOFTMAX + OUTPUT: 1 warp per head ===========================
    {
        float* srow = s_sm + wid * N_;

        float mx = -1e30f;
        for (int m = lane; m < N_; m += 32) mx = fmaxf(mx, srow[m]);
        #pragma unroll
        for (int o = 16; o > 0; o >>= 1) mx = fmaxf(mx, __shfl_xor_sync(0xffffffffu, mx, o));

        float sum = 0.f;
        for (int m = lane; m < N_; m += 32) {
            float e = __expf(srow[m] - mx);
            srow[m] = e;
            sum += e;
        }
        #pragma unroll
        for (int o = 16; o > 0; o >>= 1) sum += __shfl_xor_sync(0xffffffffu, sum, o);
        __syncwarp();

        const int d    = lane & 15;
        const int half = lane >> 4;
        const float* vp = v + (((size_t)b * H_ + wid) * N_) * D_;
        float oacc = 0.f;
        const int m0 = half * (N_ / 2);
        #pragma unroll 4
        for (int m = m0; m < m0 + N_ / 2; m++)
            oacc += srow[m] * vp[(size_t)m * D_ + d];
        oacc += __shfl_xor_sync(0xffffffffu, oacc, 16);
        if (half == 0)
            out[((size_t)b * N_ + n) * HD + wid * D_ + d] = oacc / sum;
    }
}

extern "C" void kernel_launch(void* const* d_in, const int* in_sizes, int n_in,
                              void* d_out, int out_size) {
    const float* q   = (const float*)d_in[0];
    const float* k   = (const float*)d_in[1];
    const float* v   = (const float*)d_in[2];
    const float* z   = (const float*)d_in[3];
    const float* Wz1 = (const float*)d_in[4];
    const float* Wz2 = (const float*)d_in[5];
    float* out = (float*)d_out;

    cudaFuncSetAttribute(mixed_attn_dual,
                         cudaFuncAttributeMaxDynamicSharedMemorySize, SM_TOTAL);
    dim3 grid(N_, B_);
    mixed_attn_dual<<<grid, THREADS, SM_TOTAL>>>(q, k, v, z, Wz1, Wz2, out);
}